// round 1
// baseline (speedup 1.0000x reference)
#include <cuda_runtime.h>
#include <math.h>

#define NPTS 50000
#define KNB  16
#define HALF 64
#define DIM  128
#define FPAD 132                 // padded row stride for feat/h tiles (bank-conflict relief)
#define TILES (NPTS / 4)         // 12500 tiles of 4 points (64 rows) each
#define SMEM_FLOATS (2*16384 + 256 + 2*64*FPAD)
#define SMEM_BYTES  (SMEM_FLOATS * 4)

// Scratch (allocation-free rule: __device__ globals)
__device__ float g_p0[NPTS * HALF];
__device__ float g_p1[NPTS * HALF];
__device__ float g_pl[NPTS * HALF];

// ---------------- packed f32x2 helpers (SASS FFMA2 path) ----------------
static __device__ __forceinline__ unsigned long long pack2(float lo, float hi) {
    unsigned long long r;
    asm("mov.b64 %0, {%1, %2};" : "=l"(r) : "f"(lo), "f"(hi));
    return r;
}
static __device__ __forceinline__ void unpack2(unsigned long long v, float &lo, float &hi) {
    asm("mov.b64 {%0, %1}, %2;" : "=f"(lo), "=f"(hi) : "l"(v));
}
static __device__ __forceinline__ void ffma2(unsigned long long &d,
                                             unsigned long long a,
                                             unsigned long long b) {
    asm("fma.rn.f32x2 %0, %1, %2, %0;" : "+l"(d) : "l"(a), "l"(b));
}

static __device__ __forceinline__ float gelu_exact(float x) {
    return 0.5f * x * (1.0f + erff(x * 0.70710678118654752f));
}

// ---------------- kernel 1: p0 = xyz@W1+b1 ; p1 = p0@W2+b2 ----------------
__global__ void k_p01(const float* __restrict__ xyz, const float* __restrict__ W1,
                      const float* __restrict__ b1, const float* __restrict__ W2,
                      const float* __restrict__ b2) {
    __shared__ float sp0[4][HALF];
    const int lp = threadIdx.x >> 6;   // point within block (0..3)
    const int c  = threadIdx.x & 63;   // channel
    const int i  = blockIdx.x * 4 + lp;

    float x = xyz[i * 3 + 0], y = xyz[i * 3 + 1], z = xyz[i * 3 + 2];
    float v = fmaf(z, __ldg(&W1[2 * HALF + c]), __ldg(&b1[c]));
    v = fmaf(y, __ldg(&W1[1 * HALF + c]), v);
    v = fmaf(x, __ldg(&W1[0 * HALF + c]), v);
    g_p0[i * HALF + c] = v;
    sp0[lp][c] = v;
    __syncthreads();

    float acc = __ldg(&b2[c]);
#pragma unroll
    for (int e = 0; e < HALF; e++)
        acc = fmaf(sp0[lp][e], __ldg(&W2[e * HALF + c]), acc);
    g_p1[i * HALF + c] = acc;
}

// ---------------- kernel 2: p_local = max_k (p0[knn]-p0) ----------------
__global__ void k_plocal(const int* __restrict__ knn) {
    const int lp = threadIdx.x >> 6;
    const int c  = threadIdx.x & 63;
    const int i  = blockIdx.x * 4 + lp;

    float own = g_p0[i * HALF + c];
    float m = -3.402823466e38f;
#pragma unroll
    for (int k = 0; k < KNB; k++) {
        int j = __ldg(&knn[i * KNB + k]);
        m = fmaxf(m, __ldg(&g_p0[j * HALF + c]) - own);
    }
    g_pl[i * HALF + c] = m;
}

// ---------------- kernel 3: fused edge-feature build + MLP3 ----------------
// Persistent CTAs. Per tile: 64 rows (4 points x 16 nbrs).
// feat[64][128] -> h = gelu(feat@W3a+b3a) -> out = h@W3b+b3b
__global__ void __launch_bounds__(256, 1)
k_mlp(const int* __restrict__ knn,
      const float* __restrict__ W3a, const float* __restrict__ b3a,
      const float* __restrict__ W3b, const float* __restrict__ b3b,
      float* __restrict__ out) {
    extern __shared__ float smem[];
    float* sWa = smem;                   // 128x128
    float* sWb = sWa + 16384;            // 128x128
    float* sBa = sWb + 16384;            // 128
    float* sBb = sBa + 128;              // 128
    float* sF  = sBb + 128;              // 64 x FPAD
    float* sH  = sF + 64 * FPAD;         // 64 x FPAD

    const int tid = threadIdx.x;
    for (int t = tid; t < 16384; t += 256) { sWa[t] = W3a[t]; sWb[t] = W3b[t]; }
    if (tid < 128) { sBa[tid] = b3a[tid]; sBb[tid] = b3b[tid]; }
    __syncthreads();

    const int tx = tid & 15;             // 16 col-groups of 8 cols
    const int ty = tid >> 4;             // 16 row-groups of 4 rows
    const int c0 = tx * 8;
    const int r0 = ty * 4;

    // packed bias pairs (cols c0..c0+7)
    unsigned long long ba[4], bb[4];
    {
        const ulonglong2* pa = (const ulonglong2*)(sBa + c0);
        const ulonglong2* pb = (const ulonglong2*)(sBb + c0);
        ulonglong2 a0 = pa[0], a1 = pa[1], b0 = pb[0], b1 = pb[1];
        ba[0] = a0.x; ba[1] = a0.y; ba[2] = a1.x; ba[3] = a1.y;
        bb[0] = b0.x; bb[1] = b0.y; bb[2] = b1.x; bb[3] = b1.y;
    }

    for (int tile = blockIdx.x; tile < TILES; tile += gridDim.x) {
        const int i0 = tile * 4;

        // ---- build feat tile: rows r=(p,k), cols [ps1 | p_local] ----
#pragma unroll
        for (int it = 0; it < 16; it++) {
            int idx = it * 256 + tid;
            int r = idx >> 6, e = idx & 63;
            int i = i0 + (r >> 4);
            int j = __ldg(&knn[i * KNB + (r & 15)]);
            float a  = __ldg(&g_p1[j * HALF + e]) - __ldg(&g_p1[i * HALF + e]);
            float bl = __ldg(&g_pl[i * HALF + e]);
            sF[r * FPAD + e]        = a;
            sF[r * FPAD + HALF + e] = bl;
        }
        __syncthreads();

        // ---- stage 1: H = gelu(F @ W3a + b3a) ----
        {
            unsigned long long acc[4][4];
#pragma unroll
            for (int r = 0; r < 4; r++) {
                acc[r][0] = ba[0]; acc[r][1] = ba[1];
                acc[r][2] = ba[2]; acc[r][3] = ba[3];
            }
            const float* fp = sF + r0 * FPAD;
            const float* wp = sWa + c0;
#pragma unroll 4
            for (int e = 0; e < DIM; e++) {
                ulonglong2 w0 = *(const ulonglong2*)(wp + e * DIM);
                ulonglong2 w1 = *(const ulonglong2*)(wp + e * DIM + 4);
                unsigned long long f0 = pack2(fp[0 * FPAD + e], fp[0 * FPAD + e]);
                unsigned long long f1 = pack2(fp[1 * FPAD + e], fp[1 * FPAD + e]);
                unsigned long long f2 = pack2(fp[2 * FPAD + e], fp[2 * FPAD + e]);
                unsigned long long f3 = pack2(fp[3 * FPAD + e], fp[3 * FPAD + e]);
                ffma2(acc[0][0], f0, w0.x); ffma2(acc[0][1], f0, w0.y);
                ffma2(acc[0][2], f0, w1.x); ffma2(acc[0][3], f0, w1.y);
                ffma2(acc[1][0], f1, w0.x); ffma2(acc[1][1], f1, w0.y);
                ffma2(acc[1][2], f1, w1.x); ffma2(acc[1][3], f1, w1.y);
                ffma2(acc[2][0], f2, w0.x); ffma2(acc[2][1], f2, w0.y);
                ffma2(acc[2][2], f2, w1.x); ffma2(acc[2][3], f2, w1.y);
                ffma2(acc[3][0], f3, w0.x); ffma2(acc[3][1], f3, w0.y);
                ffma2(acc[3][2], f3, w1.x); ffma2(acc[3][3], f3, w1.y);
            }
#pragma unroll
            for (int r = 0; r < 4; r++) {
#pragma unroll
                for (int p = 0; p < 4; p++) {
                    float lo, hi;
                    unpack2(acc[r][p], lo, hi);
                    lo = gelu_exact(lo); hi = gelu_exact(hi);
                    *(float2*)&sH[(r0 + r) * FPAD + c0 + 2 * p] = make_float2(lo, hi);
                }
            }
        }
        __syncthreads();

        // ---- stage 2: OUT = H @ W3b + b3b ----
        {
            unsigned long long acc[4][4];
#pragma unroll
            for (int r = 0; r < 4; r++) {
                acc[r][0] = bb[0]; acc[r][1] = bb[1];
                acc[r][2] = bb[2]; acc[r][3] = bb[3];
            }
            const float* hp = sH + r0 * FPAD;
            const float* wp = sWb + c0;
#pragma unroll 4
            for (int e = 0; e < DIM; e++) {
                ulonglong2 w0 = *(const ulonglong2*)(wp + e * DIM);
                ulonglong2 w1 = *(const ulonglong2*)(wp + e * DIM + 4);
                unsigned long long f0 = pack2(hp[0 * FPAD + e], hp[0 * FPAD + e]);
                unsigned long long f1 = pack2(hp[1 * FPAD + e], hp[1 * FPAD + e]);
                unsigned long long f2 = pack2(hp[2 * FPAD + e], hp[2 * FPAD + e]);
                unsigned long long f3 = pack2(hp[3 * FPAD + e], hp[3 * FPAD + e]);
                ffma2(acc[0][0], f0, w0.x); ffma2(acc[0][1], f0, w0.y);
                ffma2(acc[0][2], f0, w1.x); ffma2(acc[0][3], f0, w1.y);
                ffma2(acc[1][0], f1, w0.x); ffma2(acc[1][1], f1, w0.y);
                ffma2(acc[1][2], f1, w1.x); ffma2(acc[1][3], f1, w1.y);
                ffma2(acc[2][0], f2, w0.x); ffma2(acc[2][1], f2, w0.y);
                ffma2(acc[2][2], f2, w1.x); ffma2(acc[2][3], f2, w1.y);
                ffma2(acc[3][0], f3, w0.x); ffma2(acc[3][1], f3, w0.y);
                ffma2(acc[3][2], f3, w1.x); ffma2(acc[3][3], f3, w1.y);
            }
            // rows are linear: global row = tile*64 + r0 + r
#pragma unroll
            for (int r = 0; r < 4; r++) {
                float* orow = out + (size_t)(tile * 64 + r0 + r) * DIM + c0;
#pragma unroll
                for (int p = 0; p < 4; p++) {
                    float lo, hi;
                    unpack2(acc[r][p], lo, hi);
                    *(float2*)(orow + 2 * p) = make_float2(lo, hi);
                }
            }
        }
        // no sync needed here: next-iteration fill writes only sF, guarded by
        // the post-fill __syncthreads (all warps finished stage-1 reads of sF
        // before the stage-1 barrier; sH readers finish before next stage-1
        // writers pass the fill barrier).
    }
}

// ---------------- launch ----------------
extern "C" void kernel_launch(void* const* d_in, const int* in_sizes, int n_in,
                              void* d_out, int out_size) {
    const float* xyz = (const float*)d_in[0];
    const int*   knn = (const int*)d_in[1];
    const float* W1  = (const float*)d_in[2];
    const float* b1  = (const float*)d_in[3];
    const float* W2  = (const float*)d_in[4];
    const float* b2  = (const float*)d_in[5];
    const float* W3a = (const float*)d_in[6];
    const float* b3a = (const float*)d_in[7];
    const float* W3b = (const float*)d_in[8];
    const float* b3b = (const float*)d_in[9];
    float* out = (float*)d_out;

    k_p01<<<NPTS / 4, 256>>>(xyz, W1, b1, W2, b2);
    k_plocal<<<NPTS / 4, 256>>>(knn);

    cudaFuncSetAttribute(k_mlp, cudaFuncAttributeMaxDynamicSharedMemorySize, SMEM_BYTES);
    int dev = 0, sms = 148;
    cudaGetDevice(&dev);
    cudaDeviceGetAttribute(&sms, cudaDevAttrMultiProcessorCount, dev);
    k_mlp<<<sms, 256, SMEM_BYTES>>>(knn, W3a, b3a, W3b, b3b, out);
}

// round 4
// speedup vs baseline: 2.3059x; 2.3059x over previous
#include <cuda_runtime.h>
#include <cuda_bf16.h>
#include <cstdint>
#include <math.h>

#define NPTS 50000
#define KNB  16
#define HALF 64
#define DIM  128
#define TILE_ROWS 128            // 8 points x 16 neighbors
#define TILES8 (NPTS / 8)        // 6250
#define RS    272                // smem row stride in bytes (136 bf16: 128 + 8 pad)

// ---------------- scratch (__device__ globals; no allocs allowed) -------
__device__ float g_p0[NPTS * HALF];
__device__ float g_p1[NPTS * HALF];
__device__ float g_pl[NPTS * HALF];

// ---------------- smem map (bytes): 6 x (128 x 136 bf16) tiles + biases --
#define OFF_WA_HI 0
#define OFF_WA_LO 34816
#define OFF_WB_HI 69632
#define OFF_WB_LO 104448
#define OFF_FHI   139264
#define OFF_FLO   174080
#define OFF_BA    208896
#define OFF_BB    209408
#define SMEM_BYTES 209920

// ---------------- helpers ----------------
static __device__ __forceinline__ uint32_t smem_to_u32(const void* p) {
    uint32_t a;
    asm("{ .reg .u64 t; cvta.to.shared.u64 t, %1; cvt.u32.u64 %0, t; }" : "=r"(a) : "l"(p));
    return a;
}
static __device__ __forceinline__ void ldsm_x4(uint32_t* r, uint32_t addr) {
    asm volatile("ldmatrix.sync.aligned.m8n8.x4.shared.b16 {%0,%1,%2,%3}, [%4];"
        : "=r"(r[0]), "=r"(r[1]), "=r"(r[2]), "=r"(r[3]) : "r"(addr));
}
static __device__ __forceinline__ void mma16816(float* d, const uint32_t* a, const uint32_t* b) {
    asm volatile("mma.sync.aligned.m16n8k16.row.col.f32.bf16.bf16.f32 "
        "{%0,%1,%2,%3}, {%4,%5,%6,%7}, {%8,%9}, {%0,%1,%2,%3};"
        : "+f"(d[0]), "+f"(d[1]), "+f"(d[2]), "+f"(d[3])
        : "r"(a[0]), "r"(a[1]), "r"(a[2]), "r"(a[3]), "r"(b[0]), "r"(b[1]));
}
static __device__ __forceinline__ float gelu_exact(float x) {
    return 0.5f * x * (1.0f + erff(x * 0.70710678118654752f));
}
static __device__ __forceinline__ uint32_t split_hi2(float a, float b, float &ra, float &rb) {
    __nv_bfloat16 ha = __float2bfloat16_rn(a), hb = __float2bfloat16_rn(b);
    ra = a - __bfloat162float(ha);
    rb = b - __bfloat162float(hb);
    __nv_bfloat162 p; p.x = ha; p.y = hb;
    return *(uint32_t*)&p;
}
static __device__ __forceinline__ uint32_t pack_bf2(float a, float b) {
    __nv_bfloat162 p; p.x = __float2bfloat16_rn(a); p.y = __float2bfloat16_rn(b);
    return *(uint32_t*)&p;
}

// 3-split GEMM accumulate: acc += Ahi*Bhi + Ahi*Blo + Alo*Bhi
// A bases already include the warp's 16-row offset. B is [n][k] bf16, stride RS.
static __device__ __forceinline__ void gemm_split(
    uint32_t aHiBase, uint32_t aLoBase, uint32_t wHiBase, uint32_t wLoBase,
    int lane, float (&acc)[16][4])
{
    const uint32_t aOff = (uint32_t)(lane & 15) * RS + (uint32_t)(lane >> 4) * 16;
    const uint32_t bOff = ((uint32_t)(lane & 7) + ((uint32_t)(lane >> 4) & 1) * 8) * RS
                        + ((uint32_t)(lane >> 3) & 1) * 16;
#pragma unroll
    for (int ks = 0; ks < 8; ks++) {
        const uint32_t ka = ks * 32;
        uint32_t aHi[4], aLo[4];
        ldsm_x4(aHi, aHiBase + aOff + ka);
        ldsm_x4(aLo, aLoBase + aOff + ka);
#pragma unroll
        for (int ntp = 0; ntp < 8; ntp++) {
            uint32_t bHi[4], bLo[4];
            ldsm_x4(bHi, wHiBase + bOff + (uint32_t)ntp * 16 * RS + ka);
            ldsm_x4(bLo, wLoBase + bOff + (uint32_t)ntp * 16 * RS + ka);
            mma16816(acc[2 * ntp],     aHi, bHi);
            mma16816(acc[2 * ntp + 1], aHi, bHi + 2);
            mma16816(acc[2 * ntp],     aHi, bLo);
            mma16816(acc[2 * ntp + 1], aHi, bLo + 2);
            mma16816(acc[2 * ntp],     aLo, bHi);
            mma16816(acc[2 * ntp + 1], aLo, bHi + 2);
        }
    }
}

// ---------------- kernel 1: p0 = xyz@W1+b1 ; p1 = p0@W2+b2 ----------------
__global__ void k_p01(const float* __restrict__ xyz, const float* __restrict__ W1,
                      const float* __restrict__ b1, const float* __restrict__ W2,
                      const float* __restrict__ b2) {
    __shared__ float sp0[4][HALF];
    const int lp = threadIdx.x >> 6;
    const int c  = threadIdx.x & 63;
    const int i  = blockIdx.x * 4 + lp;

    float x = xyz[i * 3 + 0], y = xyz[i * 3 + 1], z = xyz[i * 3 + 2];
    float v = fmaf(z, __ldg(&W1[2 * HALF + c]), __ldg(&b1[c]));
    v = fmaf(y, __ldg(&W1[1 * HALF + c]), v);
    v = fmaf(x, __ldg(&W1[0 * HALF + c]), v);
    g_p0[i * HALF + c] = v;
    sp0[lp][c] = v;
    __syncthreads();

    float acc = __ldg(&b2[c]);
#pragma unroll
    for (int e = 0; e < HALF; e++)
        acc = fmaf(sp0[lp][e], __ldg(&W2[e * HALF + c]), acc);
    g_p1[i * HALF + c] = acc;
}

// ---------------- kernel 2: p_local = max_k (p0[knn]-p0) ----------------
__global__ void k_plocal(const int* __restrict__ knn) {
    const int lp = threadIdx.x >> 6;
    const int c  = threadIdx.x & 63;
    const int i  = blockIdx.x * 4 + lp;

    float own = g_p0[i * HALF + c];
    float m = -3.402823466e38f;
#pragma unroll
    for (int k = 0; k < KNB; k++) {
        int j = __ldg(&knn[i * KNB + k]);
        m = fmaxf(m, __ldg(&g_p0[j * HALF + c]) - own);
    }
    g_pl[i * HALF + c] = m;
}

// ---------------- kernel 3: fused edge MLP on mma.sync bf16 ----------------
__global__ void __launch_bounds__(256, 1)
k_mlp(const int* __restrict__ knn,
      const float* __restrict__ W3a, const float* __restrict__ b3a,
      const float* __restrict__ W3b, const float* __restrict__ b3b,
      float* __restrict__ out) {
    extern __shared__ char smem[];
    const uint32_t sbase = smem_to_u32(smem);
    const int tid  = threadIdx.x;
    const int wid  = tid >> 5;
    const int lane = tid & 31;
    const int warpRow = wid * 16;

    float* sBa = (float*)(smem + OFF_BA);
    float* sBb = (float*)(smem + OFF_BB);

    // ---- load + split weights (stored [n][k] = W[k][n], bf16 hi/lo) ----
    for (int idx = tid; idx < 8192; idx += 256) {
        int n = idx >> 6, ep = idx & 63, k = ep << 1;
        uint32_t off = (uint32_t)n * RS + (uint32_t)k * 2;
        float a0 = __ldg(&W3a[k * DIM + n]);
        float a1 = __ldg(&W3a[(k + 1) * DIM + n]);
        float ra0, ra1;
        *(uint32_t*)(smem + OFF_WA_HI + off) = split_hi2(a0, a1, ra0, ra1);
        *(uint32_t*)(smem + OFF_WA_LO + off) = pack_bf2(ra0, ra1);
        float b0 = __ldg(&W3b[k * DIM + n]);
        float b1v = __ldg(&W3b[(k + 1) * DIM + n]);
        float rb0, rb1;
        *(uint32_t*)(smem + OFF_WB_HI + off) = split_hi2(b0, b1v, rb0, rb1);
        *(uint32_t*)(smem + OFF_WB_LO + off) = pack_bf2(rb0, rb1);
    }
    if (tid < 128) { sBa[tid] = __ldg(&b3a[tid]); sBb[tid] = __ldg(&b3b[tid]); }
    __syncthreads();

    const uint32_t fHiW = sbase + OFF_FHI + (uint32_t)warpRow * RS;   // warp's A rows
    const uint32_t fLoW = sbase + OFF_FLO + (uint32_t)warpRow * RS;
    const int qr = lane >> 2;            // 0..7  (row within half-tile)
    const int qc = (lane & 3) * 2;       // 0,2,4,6 (col pair within n-tile)

    for (int tile = blockIdx.x; tile < TILES8; tile += gridDim.x) {
        const int i0 = tile * 8;

        // ---- cooperative fill of F hi/lo [128 rows x 128 k] ----
        for (int idx = tid; idx < 8192; idx += 256) {
            int r = idx >> 6, ep = idx & 63, e = ep << 1;
            int i = i0 + (r >> 4);
            int j = __ldg(&knn[i * KNB + (r & 15)]);
            float2 v;
            if (e < HALF) {
                float2 a = *(const float2*)&g_p1[j * HALF + e];
                float2 b = *(const float2*)&g_p1[i * HALF + e];
                v = make_float2(a.x - b.x, a.y - b.y);
            } else {
                v = *(const float2*)&g_pl[i * HALF + (e - HALF)];
            }
            uint32_t off = (uint32_t)r * RS + (uint32_t)e * 2;
            float r0, r1;
            *(uint32_t*)(smem + OFF_FHI + off) = split_hi2(v.x, v.y, r0, r1);
            *(uint32_t*)(smem + OFF_FLO + off) = pack_bf2(r0, r1);
        }
        __syncthreads();

        // ---- GEMM1: acc = F @ W3a ----
        float acc[16][4];
#pragma unroll
        for (int t = 0; t < 16; t++) { acc[t][0] = acc[t][1] = acc[t][2] = acc[t][3] = 0.f; }
        gemm_split(fHiW, fLoW, sbase + OFF_WA_HI, sbase + OFF_WA_LO, lane, acc);

        // ---- epilogue 1: +b3a, gelu, re-split into F buffers (own rows) ----
#pragma unroll
        for (int nt = 0; nt < 16; nt++) {
            int c = nt * 8 + qc;
            float bb0 = sBa[c], bb1 = sBa[c + 1];
            float g0 = gelu_exact(acc[nt][0] + bb0);
            float g1 = gelu_exact(acc[nt][1] + bb1);
            float g2 = gelu_exact(acc[nt][2] + bb0);
            float g3 = gelu_exact(acc[nt][3] + bb1);
            uint32_t o0 = (uint32_t)(warpRow + qr) * RS + (uint32_t)c * 2;
            uint32_t o1 = o0 + 8u * RS;
            float r0, r1;
            *(uint32_t*)(smem + OFF_FHI + o0) = split_hi2(g0, g1, r0, r1);
            *(uint32_t*)(smem + OFF_FLO + o0) = pack_bf2(r0, r1);
            *(uint32_t*)(smem + OFF_FHI + o1) = split_hi2(g2, g3, r0, r1);
            *(uint32_t*)(smem + OFF_FLO + o1) = pack_bf2(r0, r1);
        }
        __syncwarp();   // cross-lane visibility for ldmatrix in GEMM2

        // ---- GEMM2: acc = H @ W3b ----
#pragma unroll
        for (int t = 0; t < 16; t++) { acc[t][0] = acc[t][1] = acc[t][2] = acc[t][3] = 0.f; }
        gemm_split(fHiW, fLoW, sbase + OFF_WB_HI, sbase + OFF_WB_LO, lane, acc);

        // ---- epilogue 2: +b3b, store ----
        {
            float* obase = out + (size_t)(tile * TILE_ROWS + warpRow) * DIM;
#pragma unroll
            for (int nt = 0; nt < 16; nt++) {
                int c = nt * 8 + qc;
                float bb0 = sBb[c], bb1 = sBb[c + 1];
                *(float2*)(obase + (size_t)qr * DIM + c) =
                    make_float2(acc[nt][0] + bb0, acc[nt][1] + bb1);
                *(float2*)(obase + (size_t)(qr + 8) * DIM + c) =
                    make_float2(acc[nt][2] + bb0, acc[nt][3] + bb1);
            }
        }
        __syncthreads();   // all warps done reading F/H before next fill
    }
}

// ---------------- launch ----------------
extern "C" void kernel_launch(void* const* d_in, const int* in_sizes, int n_in,
                              void* d_out, int out_size) {
    const float* xyz = (const float*)d_in[0];
    const int*   knn = (const int*)d_in[1];
    const float* W1  = (const float*)d_in[2];
    const float* b1  = (const float*)d_in[3];
    const float* W2  = (const float*)d_in[4];
    const float* b2  = (const float*)d_in[5];
    const float* W3a = (const float*)d_in[6];
    const float* b3a = (const float*)d_in[7];
    const float* W3b = (const float*)d_in[8];
    const float* b3b = (const float*)d_in[9];
    float* out = (float*)d_out;

    k_p01<<<NPTS / 4, 256>>>(xyz, W1, b1, W2, b2);
    k_plocal<<<NPTS / 4, 256>>>(knn);

    cudaFuncSetAttribute(k_mlp, cudaFuncAttributeMaxDynamicSharedMemorySize, SMEM_BYTES);
    int dev = 0, sms = 148;
    cudaGetDevice(&dev);
    cudaDeviceGetAttribute(&sms, cudaDevAttrMultiProcessorCount, dev);
    k_mlp<<<sms, 256, SMEM_BYTES>>>(knn, W3a, b3a, W3b, b3b, out);
}